// round 3
// baseline (speedup 1.0000x reference)
#include <cuda_runtime.h>
#include <math.h>

#define BATCH    16
#define NBOX     120000
#define NCH      22
#define NMS_MAX  400
#define NUM_PRED 10
#define BINS     1024
#define HBLK     64          // extract blocks per batch
#define CAP      2048
#define MASKW    7           // ceil(400/64)

// ---------------- scratch (device globals; no runtime alloc) ----------------
__device__ float              g_scores[BATCH][NBOX];
__device__ unsigned int       g_phist[BATCH][HBLK][BINS];  // fully overwritten
__device__ int                g_cut[BATCH];
__device__ int                g_cnt[BATCH];
__device__ unsigned long long g_cand[BATCH][CAP];

// monotonic float->uint key
__device__ __forceinline__ unsigned int fkey(float f) {
    unsigned int u = __float_as_uint(f);
    return (u & 0x80000000u) ? ~u : (u | 0x80000000u);
}
__device__ __forceinline__ float fkey_inv(unsigned int k) {
    unsigned int u = (k & 0x80000000u) ? (k & 0x7fffffffu) : ~k;
    return __uint_as_float(u);
}
__device__ __forceinline__ int score_bin(float s) {
    int b = (int)(s * (float)BINS);
    if (b < 0) b = 0;
    if (b > BINS - 1) b = BINS - 1;
    return b;
}

// ============ L1: score extraction + per-block histogram =====================
__global__ void k_extract(const float* __restrict__ y) {
    __shared__ unsigned int sh[BINS];
    int b = blockIdx.y;
    for (int i = threadIdx.x; i < BINS; i += blockDim.x) sh[i] = 0u;
    __syncthreads();
    const float* base = y + (size_t)b * NBOX * NCH + 1;
    int stride = gridDim.x * blockDim.x;
    int i = blockIdx.x * blockDim.x + threadIdx.x;
    // process 2 per iteration to expose more MLP ahead of the shared atomics
    for (; i + stride < NBOX; i += 2 * stride) {
        float s0 = __ldcs(&base[(size_t)i * NCH]);
        float s1 = __ldcs(&base[(size_t)(i + stride) * NCH]);
        g_scores[b][i]          = s0;
        g_scores[b][i + stride] = s1;
        atomicAdd(&sh[score_bin(s0)], 1u);
        atomicAdd(&sh[score_bin(s1)], 1u);
    }
    if (i < NBOX) {
        float s = __ldcs(&base[(size_t)i * NCH]);
        g_scores[b][i] = s;
        atomicAdd(&sh[score_bin(s)], 1u);
    }
    __syncthreads();
    for (int k = threadIdx.x; k < BINS; k += blockDim.x)
        g_phist[b][blockIdx.x][k] = sh[k];
}

// ============ L2: reduce hist + cutoff + zero counters =======================
__global__ void k_cut() {
    __shared__ unsigned int hist[BINS];
    int b = blockIdx.x;
    int tid = threadIdx.x, lane = tid & 31;
    if (tid < BINS) {
        unsigned int s = 0;
#pragma unroll 8
        for (int k = 0; k < HBLK; ++k) s += g_phist[b][k][tid];
        hist[tid] = s;
    }
    __syncthreads();
    if (tid < 32) {
        int cum = 0, cut = 0;
        for (int base = BINS - 32; base >= 0; base -= 32) {
            int p = (int)hist[base + 31 - lane];     // lane 0 = highest bin
#pragma unroll
            for (int o = 1; o < 32; o <<= 1) {
                int t = __shfl_up_sync(0xffffffffu, p, o);
                if (lane >= o) p += t;
            }
            unsigned ball = __ballot_sync(0xffffffffu, cum + p >= NMS_MAX);
            if (ball) { cut = base + 31 - (__ffs(ball) - 1); break; }
            cum += __shfl_sync(0xffffffffu, p, 31);
        }
        if (lane == 0) { g_cut[b] = cut; g_cnt[b] = 0; }
    }
}

// ============ L3: wide gather of candidates ==================================
__global__ void k_gather() {
    int b = blockIdx.y;
    int cut = g_cut[b];
    const float4* sp = (const float4*)g_scores[b];
    int stride = gridDim.x * blockDim.x;
    for (int i4 = blockIdx.x * blockDim.x + threadIdx.x; i4 < NBOX / 4; i4 += stride) {
        float4 v = sp[i4];
        float vv[4] = {v.x, v.y, v.z, v.w};
#pragma unroll
        for (int k = 0; k < 4; ++k) {
            if (score_bin(vv[k]) >= cut) {
                int p = atomicAdd(&g_cnt[b], 1);
                if (p < CAP) {
                    unsigned int idx = (unsigned int)(i4 * 4 + k);
                    g_cand[b][p] = ((unsigned long long)fkey(vv[k]) << 32) |
                                   (unsigned long long)(~idx);
                }
            }
        }
    }
}

// ============ L4: sort + decode + NMS + output ===============================
// shared overlay:  cand u64[2048] @0 (16 KB)  -> later ov u64[400*7] @0 (22.4 KB)
//                  sc f32[400] @22400, sidx i32[400] @24000, bx f32[1600] @25600
#define OFF_OVL  0
#define OFF_SC   22400
#define OFF_SIDX 24000
#define OFF_BX   25600
#define SMEM_SZ  (25600 + 6400)

__global__ __launch_bounds__(1024, 1)
void k_nms(const float* __restrict__ y, float* __restrict__ out) {
    __shared__ __align__(16) unsigned char buf[SMEM_SZ];
    __shared__ unsigned long long keepm[MASKW];
    __shared__ int sel[NUM_PRED], selk[NUM_PRED];
    __shared__ int pp[MASKW + 1];

    unsigned long long* cand = (unsigned long long*)(buf + OFF_OVL);
    unsigned long long* ov   = (unsigned long long*)(buf + OFF_OVL);
    float* sc  = (float*)(buf + OFF_SC);
    int*   sidx= (int*)(buf + OFF_SIDX);
    float* bx  = (float*)(buf + OFF_BX);

    int b = blockIdx.x;
    int tid = threadIdx.x, lane = tid & 31;

    int cnt = g_cnt[b]; if (cnt > CAP) cnt = CAP;
    int n = 1; while (n < cnt) n <<= 1;          // power of two >= cnt (>=512 here)
    for (int i = tid; i < n; i += 1024)
        cand[i] = (i < cnt) ? g_cand[b][i] : 0ULL;
    __syncthreads();

    // --- bitonic sort, DESCENDING ---
    for (int k = 2; k <= n; k <<= 1) {
        for (int j = k >> 1; j > 0; j >>= 1) {
            for (int i = tid; i < n; i += 1024) {
                int ixj = i ^ j;
                if (ixj > i) {
                    bool up = ((i & k) == 0);
                    unsigned long long a = cand[i], c = cand[ixj];
                    if (up ? (a < c) : (a > c)) { cand[i] = c; cand[ixj] = a; }
                }
            }
            __syncthreads();
        }
    }

    // --- top-400: decode corner boxes ---
    if (tid < NMS_MAX) {
        unsigned long long key = cand[tid];
        float s = fkey_inv((unsigned int)(key >> 32));
        unsigned int idx = ~(unsigned int)(key & 0xffffffffu);
        if (idx >= NBOX) idx = 0;
        sc[tid] = s;
        sidx[tid] = (int)idx;
        const float* r = y + ((size_t)b * NBOX + idx) * NCH;
        float l0 = r[2], l1 = r[3], l2 = r[4], l3 = r[5];
        float dcx = r[14], dcy = r[15], dw = r[16], dh = r[17];
        float v0 = r[18], v1 = r[19], v2 = r[20], v3 = r[21];
        float cx = l0 * v0 * dw + dcx;
        float cy = l1 * v1 * dh + dcy;
        float w  = expf(l2 * v2) * dw;
        float h  = expf(l3 * v3) * dh;
        bx[tid*4+0] = (cx - w * 0.5f) * 384.0f;
        bx[tid*4+1] = (cy - h * 0.5f) * 384.0f;
        bx[tid*4+2] = (cx + w * 0.5f) * 384.0f;
        bx[tid*4+3] = (cy + h * 0.5f) * 384.0f;
    }
    __syncthreads();                 // cand dead; ov overlays it

    // --- IoU overlap bitmasks ---
    for (int p = tid; p < NMS_MAX * MASKW; p += 1024) {
        int i = p / MASKW, w = p % MASKW;
        float ax0 = bx[i*4+0], ay0 = bx[i*4+1], ax1 = bx[i*4+2], ay1 = bx[i*4+3];
        float areai = (ax1 - ax0) * (ay1 - ay0);
        unsigned long long m = 0ULL;
        int j0 = w * 64;
        int j1 = j0 + 64; if (j1 > NMS_MAX) j1 = NMS_MAX;
        for (int j = j0; j < j1; ++j) {
            float cx0 = bx[j*4+0], cy0 = bx[j*4+1], cx1 = bx[j*4+2], cy1 = bx[j*4+3];
            float lt0 = fmaxf(ax0, cx0), lt1 = fmaxf(ay0, cy0);
            float rb0 = fminf(ax1, cx1), rb1 = fminf(ay1, cy1);
            float w0 = fmaxf(rb0 - lt0, 0.0f);
            float w1 = fmaxf(rb1 - lt1, 0.0f);
            float inter = w0 * w1;
            float areaj = (cx1 - cx0) * (cy1 - cy0);
            float uni = areai + areaj - inter;
            if (inter / fmaxf(uni, 1e-8f) > 0.45f) m |= 1ULL << (j - j0);
        }
        ov[i * MASKW + w] = m;
    }
    __syncthreads();

    // --- skip-ahead greedy NMS (warp 0): pop next live candidate, kill its row
    if (tid < 32) {
        unsigned long long validw = 0ULL;
        if (lane < MASKW) {
            int j0 = lane * 64, j1 = j0 + 64; if (j1 > NMS_MAX) j1 = NMS_MAX;
            for (int j = j0; j < j1; ++j)
                if (sc[j] > 0.01f) validw |= 1ULL << (j - j0);
        }
        unsigned long long dead = 0ULL, keep = 0ULL;
        for (int it = 0; it < NMS_MAX; ++it) {
            unsigned long long w = (lane < MASKW) ? (validw & ~dead) : 0ULL;
            unsigned ball = __ballot_sync(0xffffffffu, w != 0ULL);
            if (!ball) break;
            int l0 = __ffs(ball) - 1;
            unsigned long long wl = __shfl_sync(0xffffffffu, w, l0);
            int i = l0 * 64 + (__ffsll((long long)wl) - 1);
            if (lane == l0) keep |= 1ULL << (i & 63);
            unsigned long long row = (lane < MASKW) ? ov[i * MASKW + lane] : 0ULL;
            dead |= row;                         // includes diagonal bit i
            if (lane == l0) dead |= 1ULL << (i & 63);
        }
        if (lane < MASKW) keepm[lane] = keep;
    }
    __syncthreads();

    // --- parallel selection ---
    if (tid == 0) {
        pp[0] = 0;
        for (int w = 0; w < MASKW; ++w) pp[w + 1] = pp[w] + __popcll(keepm[w]);
    }
    __syncthreads();
    if (tid < NMS_MAX) {
        int w = tid >> 6, bit = tid & 63;
        unsigned long long below = keepm[w] & ((bit == 0) ? 0ULL : ((~0ULL) >> (64 - bit)));
        int keptBefore = pp[w] + __popcll(below);
        bool kept = (keepm[w] >> bit) & 1ULL;
        int K = pp[MASKW];
        if (kept) {
            if (keptBefore < NUM_PRED) { sel[keptBefore] = tid; selk[keptBefore] = 1; }
        } else {
            int r = K + (tid - keptBefore);
            if (r < NUM_PRED) { sel[r] = tid; selk[r] = 0; }
        }
    }
    __syncthreads();

    // --- output rows: [score, box4, quad8] ---
    if (tid < NUM_PRED) {
        int i = sel[tid];
        float* o = out + ((size_t)b * NUM_PRED + tid) * 13;
        o[0] = selk[tid] ? sc[i] : -1.0f;
        o[1] = bx[i*4+0]; o[2] = bx[i*4+1]; o[3] = bx[i*4+2]; o[4] = bx[i*4+3];
        const float* r = y + ((size_t)b * NBOX + sidx[i]) * NCH;
        float dcx = r[14], dcy = r[15], dw = r[16], dh = r[17];
        float v0 = r[18], v1 = r[19];
        float dqx[4] = {dcx - dw*0.5f, dcx + dw*0.5f, dcx + dw*0.5f, dcx - dw*0.5f};
        float dqy[4] = {dcy - dh*0.5f, dcy - dh*0.5f, dcy + dh*0.5f, dcy + dh*0.5f};
#pragma unroll
        for (int k = 0; k < 4; ++k) {
            float qx = dqx[k] + r[6 + 2*k] * v0 * dw;
            float qy = dqy[k] + r[7 + 2*k] * v1 * dh;
            o[5 + 2*k]     = qx * 384.0f;
            o[5 + 2*k + 1] = qy * 384.0f;
        }
    }
}

// ---------------- launch ---------------------------------------------------
extern "C" void kernel_launch(void* const* d_in, const int* in_sizes, int n_in,
                              void* d_out, int out_size) {
    const float* y = (const float*)d_in[0];
    float* out = (float*)d_out;
    k_extract<<<dim3(HBLK, BATCH), 256>>>(y);
    k_cut<<<BATCH, 1024>>>();
    k_gather<<<dim3(32, BATCH), 256>>>();
    k_nms<<<BATCH, 1024>>>(y, out);
}

// round 4
// speedup vs baseline: 1.1346x; 1.1346x over previous
#include <cuda_runtime.h>
#include <math.h>

#define BATCH    16
#define NBOX     120000
#define NCH      22
#define NMS_MAX  400
#define NUM_PRED 10
#define BINS     1024
#define HBLK     64          // extract blocks per batch
#define CAP      1024        // sort width (register sort, 1 elem/thread)
#define MASKW    7           // ceil(400/64)

// ---------------- scratch (device globals; no runtime alloc) ----------------
__device__ float              g_scores[BATCH][NBOX];
__device__ unsigned int       g_phist[BATCH][HBLK][BINS];  // fully overwritten
__device__ int                g_cut[BATCH];
__device__ int                g_cnt[BATCH];
__device__ unsigned long long g_cand[BATCH][CAP];

// monotonic float->uint key
__device__ __forceinline__ unsigned int fkey(float f) {
    unsigned int u = __float_as_uint(f);
    return (u & 0x80000000u) ? ~u : (u | 0x80000000u);
}
__device__ __forceinline__ float fkey_inv(unsigned int k) {
    unsigned int u = (k & 0x80000000u) ? (k & 0x7fffffffu) : ~k;
    return __uint_as_float(u);
}
__device__ __forceinline__ int score_bin(float s) {
    int b = (int)(s * (float)BINS);
    if (b < 0) b = 0;
    if (b > BINS - 1) b = BINS - 1;
    return b;
}

// ============ L1: score extraction + per-block histogram =====================
__global__ void k_extract(const float* __restrict__ y) {
    __shared__ unsigned int sh[BINS];
    int b = blockIdx.y;
    for (int i = threadIdx.x; i < BINS; i += blockDim.x) sh[i] = 0u;
    __syncthreads();
    const float* base = y + (size_t)b * NBOX * NCH + 1;
    int stride = gridDim.x * blockDim.x;
    int i = blockIdx.x * blockDim.x + threadIdx.x;
    for (; i + stride < NBOX; i += 2 * stride) {
        float s0 = __ldcs(&base[(size_t)i * NCH]);
        float s1 = __ldcs(&base[(size_t)(i + stride) * NCH]);
        g_scores[b][i]          = s0;
        g_scores[b][i + stride] = s1;
        atomicAdd(&sh[score_bin(s0)], 1u);
        atomicAdd(&sh[score_bin(s1)], 1u);
    }
    if (i < NBOX) {
        float s = __ldcs(&base[(size_t)i * NCH]);
        g_scores[b][i] = s;
        atomicAdd(&sh[score_bin(s)], 1u);
    }
    __syncthreads();
    for (int k = threadIdx.x; k < BINS; k += blockDim.x)
        g_phist[b][blockIdx.x][k] = sh[k];
}

// ============ L2: reduce hist + cutoff + zero counters =======================
__global__ void k_cut() {
    __shared__ unsigned int hist[BINS];
    int b = blockIdx.x;
    int tid = threadIdx.x, lane = tid & 31;
    if (tid < BINS) {
        unsigned int s = 0;
#pragma unroll 8
        for (int k = 0; k < HBLK; ++k) s += g_phist[b][k][tid];
        hist[tid] = s;
    }
    __syncthreads();
    if (tid < 32) {
        int cum = 0, cut = 0;
        for (int base = BINS - 32; base >= 0; base -= 32) {
            int p = (int)hist[base + 31 - lane];     // lane 0 = highest bin
#pragma unroll
            for (int o = 1; o < 32; o <<= 1) {
                int t = __shfl_up_sync(0xffffffffu, p, o);
                if (lane >= o) p += t;
            }
            unsigned ball = __ballot_sync(0xffffffffu, cum + p >= NMS_MAX);
            if (ball) { cut = base + 31 - (__ffs(ball) - 1); break; }
            cum += __shfl_sync(0xffffffffu, p, 31);
        }
        if (lane == 0) { g_cut[b] = cut; g_cnt[b] = 0; }
    }
}

// ============ L3: wide gather of candidates ==================================
__global__ void k_gather() {
    int b = blockIdx.y;
    int cut = g_cut[b];
    const float4* sp = (const float4*)g_scores[b];
    int stride = gridDim.x * blockDim.x;
    for (int i4 = blockIdx.x * blockDim.x + threadIdx.x; i4 < NBOX / 4; i4 += stride) {
        float4 v = sp[i4];
        float vv[4] = {v.x, v.y, v.z, v.w};
#pragma unroll
        for (int k = 0; k < 4; ++k) {
            if (score_bin(vv[k]) >= cut) {
                int p = atomicAdd(&g_cnt[b], 1);
                if (p < CAP) {
                    unsigned int idx = (unsigned int)(i4 * 4 + k);
                    g_cand[b][p] = ((unsigned long long)fkey(vv[k]) << 32) |
                                   (unsigned long long)(~idx);
                }
            }
        }
    }
}

// ============ L4: register sort + decode + NMS + output =====================
// shared overlay: sort exchange u64[1024] (8KB) then ov u64[400*7] (22400B)
#define OFF_OVL  0
#define OFF_SC   22400
#define OFF_SIDX 24000
#define OFF_BX   25600
#define SMEM_SZ  (25600 + 6400)

__global__ __launch_bounds__(1024, 1)
void k_nms(const float* __restrict__ y, float* __restrict__ out) {
    __shared__ __align__(16) unsigned char buf[SMEM_SZ];
    __shared__ unsigned long long keepw[MASKW];
    __shared__ unsigned int vw[2];
    __shared__ int sel[NUM_PRED], selk[NUM_PRED];
    __shared__ int pp[MASKW + 1];

    unsigned long long* xbuf = (unsigned long long*)(buf + OFF_OVL); // sort exchange
    unsigned long long* ov   = (unsigned long long*)(buf + OFF_OVL); // after sort
    float* sc   = (float*)(buf + OFF_SC);
    int*   sidx = (int*)(buf + OFF_SIDX);
    float* bx   = (float*)(buf + OFF_BX);

    int b = blockIdx.x;
    int tid = threadIdx.x;

    int cnt = g_cnt[b]; if (cnt > CAP) cnt = CAP;
    unsigned long long v = (tid < cnt) ? g_cand[b][tid] : 0ULL;

    // --- hybrid bitonic sort of 1024 keys, DESCENDING; thread i ends with rank i
#pragma unroll
    for (int k = 2; k <= 1024; k <<= 1) {
#pragma unroll
        for (int j = k >> 1; j > 0; j >>= 1) {
            bool keep_max = (((tid & j) == 0) == ((tid & k) == 0));
            unsigned long long o;
            if (j < 32) {
                o = __shfl_xor_sync(0xffffffffu, v, j);
            } else {
                xbuf[tid] = v;
                __syncthreads();
                o = xbuf[tid ^ j];
                __syncthreads();
            }
            unsigned long long mx = (v > o) ? v : o;
            unsigned long long mn = (v > o) ? o : v;
            v = keep_max ? mx : mn;
        }
    }

    // --- top-400: decode corner boxes (key is in register) ---
    if (tid < NMS_MAX) {
        float s = fkey_inv((unsigned int)(v >> 32));
        unsigned int idx = ~(unsigned int)(v & 0xffffffffu);
        if (idx >= NBOX) idx = 0;
        sc[tid] = s;
        sidx[tid] = (int)idx;
        const float* r = y + ((size_t)b * NBOX + idx) * NCH;
        float l0 = r[2], l1 = r[3], l2 = r[4], l3 = r[5];
        float dcx = r[14], dcy = r[15], dw = r[16], dh = r[17];
        float v0 = r[18], v1 = r[19], v2 = r[20], v3 = r[21];
        float cx = l0 * v0 * dw + dcx;
        float cy = l1 * v1 * dh + dcy;
        float w  = expf(l2 * v2) * dw;
        float h  = expf(l3 * v3) * dh;
        bx[tid*4+0] = (cx - w * 0.5f) * 384.0f;
        bx[tid*4+1] = (cy - h * 0.5f) * 384.0f;
        bx[tid*4+2] = (cx + w * 0.5f) * 384.0f;
        bx[tid*4+3] = (cy + h * 0.5f) * 384.0f;
    }
    if (tid < MASKW) keepw[tid] = 0ULL;
    __syncthreads();                 // xbuf dead; ov overlays it

    // --- IoU overlap bitmasks ---
    for (int p = tid; p < NMS_MAX * MASKW; p += 1024) {
        int i = p / MASKW, w = p % MASKW;
        float ax0 = bx[i*4+0], ay0 = bx[i*4+1], ax1 = bx[i*4+2], ay1 = bx[i*4+3];
        float areai = (ax1 - ax0) * (ay1 - ay0);
        unsigned long long m = 0ULL;
        int j0 = w * 64;
        int j1 = j0 + 64; if (j1 > NMS_MAX) j1 = NMS_MAX;
        for (int j = j0; j < j1; ++j) {
            float cx0 = bx[j*4+0], cy0 = bx[j*4+1], cx1 = bx[j*4+2], cy1 = bx[j*4+3];
            float lt0 = fmaxf(ax0, cx0), lt1 = fmaxf(ay0, cy0);
            float rb0 = fminf(ax1, cx1), rb1 = fminf(ay1, cy1);
            float w0 = fmaxf(rb0 - lt0, 0.0f);
            float w1 = fmaxf(rb1 - lt1, 0.0f);
            float inter = w0 * w1;
            float areaj = (cx1 - cx0) * (cy1 - cy0);
            float uni = areai + areaj - inter;
            if (inter / fmaxf(uni, 1e-8f) > 0.45f) m |= 1ULL << (j - j0);
        }
        ov[i * MASKW + w] = m;
    }
    __syncthreads();

    // --- block-batched greedy NMS: exact sequential semantics ---
    // keep[i] = valid[i] && !any_{j<i}(iou>thr && keep[j])
    for (int blk = 0; blk < MASKW; ++blk) {
        // parallel: candidate i survives all previously-kept (earlier blocks)?
        bool ok = false;
        int i = blk * 64 + tid;
        if (tid < 64 && i < NMS_MAX) {
            unsigned long long hit = 0ULL;
#pragma unroll
            for (int w = 0; w < MASKW; ++w)
                hit |= ov[i * MASKW + w] & keepw[w];   // keepw[>=blk] still 0
            ok = (sc[i] > 0.01f) && (hit == 0ULL);
        }
        if (tid < 64) {
            unsigned bal = __ballot_sync(0xffffffffu, ok);
            if ((tid & 31) == 0) vw[tid >> 5] = bal;
        }
        __syncthreads();
        if (tid == 0) {
            unsigned long long cand_ok = (unsigned long long)vw[0] |
                                         ((unsigned long long)vw[1] << 32);
            unsigned long long kcur = 0ULL;
#pragma unroll 8
            for (int t = 0; t < 64; ++t) {
                if ((cand_ok >> t) & 1ULL) {
                    unsigned long long M = ov[(blk * 64 + t) * MASKW + blk];
                    if ((M & kcur) == 0ULL) kcur |= 1ULL << t;
                }
            }
            keepw[blk] = kcur;
        }
        __syncthreads();
    }

    // --- parallel selection ---
    if (tid == 0) {
        pp[0] = 0;
        for (int w = 0; w < MASKW; ++w) pp[w + 1] = pp[w] + __popcll(keepw[w]);
    }
    __syncthreads();
    if (tid < NMS_MAX) {
        int w = tid >> 6, bit = tid & 63;
        unsigned long long below = keepw[w] & ((bit == 0) ? 0ULL : ((~0ULL) >> (64 - bit)));
        int keptBefore = pp[w] + __popcll(below);
        bool kept = (keepw[w] >> bit) & 1ULL;
        int K = pp[MASKW];
        if (kept) {
            if (keptBefore < NUM_PRED) { sel[keptBefore] = tid; selk[keptBefore] = 1; }
        } else {
            int r = K + (tid - keptBefore);
            if (r < NUM_PRED) { sel[r] = tid; selk[r] = 0; }
        }
    }
    __syncthreads();

    // --- output rows: [score, box4, quad8] ---
    if (tid < NUM_PRED) {
        int i = sel[tid];
        float* o = out + ((size_t)b * NUM_PRED + tid) * 13;
        o[0] = selk[tid] ? sc[i] : -1.0f;
        o[1] = bx[i*4+0]; o[2] = bx[i*4+1]; o[3] = bx[i*4+2]; o[4] = bx[i*4+3];
        const float* r = y + ((size_t)b * NBOX + sidx[i]) * NCH;
        float dcx = r[14], dcy = r[15], dw = r[16], dh = r[17];
        float v0 = r[18], v1 = r[19];
        float dqx[4] = {dcx - dw*0.5f, dcx + dw*0.5f, dcx + dw*0.5f, dcx - dw*0.5f};
        float dqy[4] = {dcy - dh*0.5f, dcy - dh*0.5f, dcy + dh*0.5f, dcy + dh*0.5f};
#pragma unroll
        for (int k = 0; k < 4; ++k) {
            float qx = dqx[k] + r[6 + 2*k] * v0 * dw;
            float qy = dqy[k] + r[7 + 2*k] * v1 * dh;
            o[5 + 2*k]     = qx * 384.0f;
            o[5 + 2*k + 1] = qy * 384.0f;
        }
    }
}

// ---------------- launch ---------------------------------------------------
extern "C" void kernel_launch(void* const* d_in, const int* in_sizes, int n_in,
                              void* d_out, int out_size) {
    const float* y = (const float*)d_in[0];
    float* out = (float*)d_out;
    k_extract<<<dim3(HBLK, BATCH), 256>>>(y);
    k_cut<<<BATCH, 1024>>>();
    k_gather<<<dim3(32, BATCH), 256>>>();
    k_nms<<<BATCH, 1024>>>(y, out);
}

// round 5
// speedup vs baseline: 1.7643x; 1.5550x over previous
#include <cuda_runtime.h>
#include <math.h>

#define BATCH    16
#define NBOX     120000
#define NCH      22
#define NMS_MAX  400
#define NUM_PRED 10
#define BINS     1024
#define HBLK     64          // extract blocks per batch
#define CAP      1024        // sort width (register sort, 1 elem/thread)
#define MASKW    7           // ceil(400/64)

// ---------------- scratch (device globals; no runtime alloc) ----------------
__device__ float              g_scores[BATCH][NBOX];
__device__ unsigned int       g_phist[BATCH][HBLK][BINS];
__device__ int                g_cut[BATCH];
__device__ int                g_cnt[BATCH];
__device__ unsigned long long g_cand[BATCH][CAP];
__device__ float              g_sc[BATCH][NMS_MAX];
__device__ int                g_sidx[BATCH][NMS_MAX];
__device__ float              g_bx[BATCH][NMS_MAX * 4];
__device__ unsigned long long g_ov[BATCH][NMS_MAX * MASKW];

__device__ __forceinline__ unsigned int fkey(float f) {
    unsigned int u = __float_as_uint(f);
    return (u & 0x80000000u) ? ~u : (u | 0x80000000u);
}
__device__ __forceinline__ float fkey_inv(unsigned int k) {
    unsigned int u = (k & 0x80000000u) ? (k & 0x7fffffffu) : ~k;
    return __uint_as_float(u);
}
__device__ __forceinline__ int score_bin(float s) {
    int b = (int)(s * (float)BINS);
    if (b < 0) b = 0;
    if (b > BINS - 1) b = BINS - 1;
    return b;
}
__device__ __forceinline__ unsigned long long below_mask(int x) {
    return (x == 0) ? 0ULL : ((~0ULL) >> (64 - x));
}

// ============ L1: score extraction + per-block histogram =====================
__global__ void k_extract(const float* __restrict__ y) {
    __shared__ unsigned int sh[BINS];
    int b = blockIdx.y;
    for (int i = threadIdx.x; i < BINS; i += blockDim.x) sh[i] = 0u;
    __syncthreads();
    const float* base = y + (size_t)b * NBOX * NCH + 1;
    int stride = gridDim.x * blockDim.x;
    int i = blockIdx.x * blockDim.x + threadIdx.x;
    for (; i + stride < NBOX; i += 2 * stride) {
        float s0 = __ldcs(&base[(size_t)i * NCH]);
        float s1 = __ldcs(&base[(size_t)(i + stride) * NCH]);
        g_scores[b][i]          = s0;
        g_scores[b][i + stride] = s1;
        atomicAdd(&sh[score_bin(s0)], 1u);
        atomicAdd(&sh[score_bin(s1)], 1u);
    }
    if (i < NBOX) {
        float s = __ldcs(&base[(size_t)i * NCH]);
        g_scores[b][i] = s;
        atomicAdd(&sh[score_bin(s)], 1u);
    }
    __syncthreads();
    for (int k = threadIdx.x; k < BINS; k += blockDim.x)
        g_phist[b][blockIdx.x][k] = sh[k];
}

// ============ L2: reduce hist + cutoff + zero counters =======================
__global__ void k_cut() {
    __shared__ unsigned int hist[BINS];
    int b = blockIdx.x;
    int tid = threadIdx.x, lane = tid & 31;
    if (tid < BINS) {
        unsigned int s = 0;
#pragma unroll 8
        for (int k = 0; k < HBLK; ++k) s += g_phist[b][k][tid];
        hist[tid] = s;
    }
    __syncthreads();
    if (tid < 32) {
        int cum = 0, cut = 0;
        for (int base = BINS - 32; base >= 0; base -= 32) {
            int p = (int)hist[base + 31 - lane];
#pragma unroll
            for (int o = 1; o < 32; o <<= 1) {
                int t = __shfl_up_sync(0xffffffffu, p, o);
                if (lane >= o) p += t;
            }
            unsigned ball = __ballot_sync(0xffffffffu, cum + p >= NMS_MAX);
            if (ball) { cut = base + 31 - (__ffs(ball) - 1); break; }
            cum += __shfl_sync(0xffffffffu, p, 31);
        }
        if (lane == 0) { g_cut[b] = cut; g_cnt[b] = 0; }
    }
}

// ============ L3: wide gather ================================================
__global__ void k_gather() {
    int b = blockIdx.y;
    int cut = g_cut[b];
    const float4* sp = (const float4*)g_scores[b];
    int stride = gridDim.x * blockDim.x;
    for (int i4 = blockIdx.x * blockDim.x + threadIdx.x; i4 < NBOX / 4; i4 += stride) {
        float4 v = sp[i4];
        float vv[4] = {v.x, v.y, v.z, v.w};
#pragma unroll
        for (int k = 0; k < 4; ++k) {
            if (score_bin(vv[k]) >= cut) {
                int p = atomicAdd(&g_cnt[b], 1);
                if (p < CAP) {
                    unsigned int idx = (unsigned int)(i4 * 4 + k);
                    g_cand[b][p] = ((unsigned long long)fkey(vv[k]) << 32) |
                                   (unsigned long long)(~idx);
                }
            }
        }
    }
}

// ============ L4: register bitonic sort + decode ============================
__global__ __launch_bounds__(1024, 1)
void k_sortdecode(const float* __restrict__ y) {
    __shared__ unsigned long long xbuf[CAP];
    int b = blockIdx.x, tid = threadIdx.x;
    int cnt = g_cnt[b]; if (cnt > CAP) cnt = CAP;
    unsigned long long v = (tid < cnt) ? g_cand[b][tid] : 0ULL;

#pragma unroll
    for (int k = 2; k <= 1024; k <<= 1) {
#pragma unroll
        for (int j = k >> 1; j > 0; j >>= 1) {
            bool keep_max = (((tid & j) == 0) == ((tid & k) == 0));
            unsigned long long o;
            if (j < 32) {
                o = __shfl_xor_sync(0xffffffffu, v, j);
            } else {
                xbuf[tid] = v;
                __syncthreads();
                o = xbuf[tid ^ j];
                __syncthreads();
            }
            unsigned long long mx = (v > o) ? v : o;
            unsigned long long mn = (v > o) ? o : v;
            v = keep_max ? mx : mn;
        }
    }

    if (tid < NMS_MAX) {
        float s = fkey_inv((unsigned int)(v >> 32));
        unsigned int idx = ~(unsigned int)(v & 0xffffffffu);
        if (idx >= NBOX) idx = 0;
        g_sc[b][tid] = s;
        g_sidx[b][tid] = (int)idx;
        const float* r = y + ((size_t)b * NBOX + idx) * NCH;
        float l0 = r[2], l1 = r[3], l2 = r[4], l3 = r[5];
        float dcx = r[14], dcy = r[15], dw = r[16], dh = r[17];
        float v0 = r[18], v1 = r[19], v2 = r[20], v3 = r[21];
        float cx = l0 * v0 * dw + dcx;
        float cy = l1 * v1 * dh + dcy;
        float w  = expf(l2 * v2) * dw;
        float h  = expf(l3 * v3) * dh;
        g_bx[b][tid*4+0] = (cx - w * 0.5f) * 384.0f;
        g_bx[b][tid*4+1] = (cy - h * 0.5f) * 384.0f;
        g_bx[b][tid*4+2] = (cx + w * 0.5f) * 384.0f;
        g_bx[b][tid*4+3] = (cy + h * 0.5f) * 384.0f;
    }
}

// ============ L5: wide IoU bitmask build =====================================
// grid (MASKW, BATCH) x 256. All threads in a block share word w -> inner
// shared reads are pure broadcast.
__global__ void k_iou() {
    __shared__ float bxs[NMS_MAX * 4];
    int w = blockIdx.x, b = blockIdx.y, tid = threadIdx.x;
    for (int i = tid; i < NMS_MAX * 4; i += 256) bxs[i] = g_bx[b][i];
    __syncthreads();
    int j0 = w * 64;
    int j1 = j0 + 64; if (j1 > NMS_MAX) j1 = NMS_MAX;
    for (int i = tid; i < NMS_MAX; i += 256) {
        float ax0 = bxs[i*4+0], ay0 = bxs[i*4+1], ax1 = bxs[i*4+2], ay1 = bxs[i*4+3];
        float areai = (ax1 - ax0) * (ay1 - ay0);
        unsigned long long m = 0ULL;
        for (int j = j0; j < j1; ++j) {
            float cx0 = bxs[j*4+0], cy0 = bxs[j*4+1], cx1 = bxs[j*4+2], cy1 = bxs[j*4+3];
            float lt0 = fmaxf(ax0, cx0), lt1 = fmaxf(ay0, cy0);
            float rb0 = fminf(ax1, cx1), rb1 = fminf(ay1, cy1);
            float w0 = fmaxf(rb0 - lt0, 0.0f);
            float w1 = fmaxf(rb1 - lt1, 0.0f);
            float inter = w0 * w1;
            float areaj = (cx1 - cx0) * (cy1 - cy0);
            float uni = areai + areaj - inter;
            if (inter / fmaxf(uni, 1e-8f) > 0.45f) m |= 1ULL << (j - j0);
        }
        g_ov[b][i * MASKW + w] = m;
    }
}

// ============ L6: warp greedy NMS + selection + output =======================
__global__ __launch_bounds__(512, 1)
void k_greedy(const float* __restrict__ y, float* __restrict__ out) {
    __shared__ unsigned long long ovs[NMS_MAX * MASKW];
    __shared__ float scs[NMS_MAX];
    __shared__ unsigned long long keepw[MASKW];
    __shared__ int sel[NUM_PRED], selk[NUM_PRED];
    __shared__ int pp[MASKW + 1];

    int b = blockIdx.x, tid = threadIdx.x;
    for (int i = tid; i < NMS_MAX * MASKW; i += 512) ovs[i] = g_ov[b][i];
    for (int i = tid; i < NMS_MAX; i += 512) scs[i] = g_sc[b][i];
    __syncthreads();

    // --- greedy in warp 0, all state in registers ---
    if (tid < 32) {
        int t = tid;
        unsigned long long k0 = 0, k1 = 0, k2 = 0, k3 = 0, k4 = 0, k5 = 0, k6 = 0;
#pragma unroll
        for (int blk = 0; blk < MASKW; ++blk) {
            int ilo = blk * 64 + t;
            int ihi = ilo + 32;
            // suppressed by earlier kept?
            unsigned long long hlo = 0, hhi = 0;
            if (ilo < NMS_MAX) {
                hlo = (ovs[ilo*MASKW+0] & k0) | (ovs[ilo*MASKW+1] & k1) |
                      (ovs[ilo*MASKW+2] & k2) | (ovs[ilo*MASKW+3] & k3) |
                      (ovs[ilo*MASKW+4] & k4) | (ovs[ilo*MASKW+5] & k5) |
                      (ovs[ilo*MASKW+6] & k6);
            }
            if (ihi < NMS_MAX) {
                hhi = (ovs[ihi*MASKW+0] & k0) | (ovs[ihi*MASKW+1] & k1) |
                      (ovs[ihi*MASKW+2] & k2) | (ovs[ihi*MASKW+3] & k3) |
                      (ovs[ihi*MASKW+4] & k4) | (ovs[ihi*MASKW+5] & k5) |
                      (ovs[ihi*MASKW+6] & k6);
            }
            bool oklo = (ilo < NMS_MAX) && (scs[ilo] > 0.01f) && (hlo == 0ULL);
            bool okhi = (ihi < NMS_MAX) && (scs[ihi] > 0.01f) && (hhi == 0ULL);
            unsigned blo = __ballot_sync(0xffffffffu, oklo);
            unsigned bhi = __ballot_sync(0xffffffffu, okhi);
            unsigned long long K = (unsigned long long)blo |
                                   ((unsigned long long)bhi << 32);
            // within-block masks (bits strictly below own index)
            unsigned long long Mlo = (ilo < NMS_MAX)
                ? (ovs[ilo*MASKW+blk] & below_mask(t)) : 0ULL;
            unsigned long long Mhi = (ihi < NMS_MAX)
                ? (ovs[ihi*MASKW+blk] & below_mask(t + 32)) : 0ULL;
            // iterative first-bad removal (exact greedy)
            while (true) {
                bool badlo = ((K >> t) & 1ULL) && (Mlo & K);
                bool badhi = ((K >> (t + 32)) & 1ULL) && (Mhi & K);
                unsigned bl = __ballot_sync(0xffffffffu, badlo);
                unsigned bh = __ballot_sync(0xffffffffu, badhi);
                unsigned long long bad = (unsigned long long)bl |
                                         ((unsigned long long)bh << 32);
                if (!bad) break;
                K &= ~(bad & (0ULL - bad));   // clear lowest bad bit
            }
            if (blk == 0) k0 = K; else if (blk == 1) k1 = K;
            else if (blk == 2) k2 = K; else if (blk == 3) k3 = K;
            else if (blk == 4) k4 = K; else if (blk == 5) k5 = K;
            else k6 = K;
        }
        if (t == 0) {
            keepw[0]=k0; keepw[1]=k1; keepw[2]=k2; keepw[3]=k3;
            keepw[4]=k4; keepw[5]=k5; keepw[6]=k6;
            pp[0] = 0;
            pp[1] = __popcll(k0);               pp[2] = pp[1] + __popcll(k1);
            pp[3] = pp[2] + __popcll(k2);       pp[4] = pp[3] + __popcll(k3);
            pp[5] = pp[4] + __popcll(k4);       pp[6] = pp[5] + __popcll(k5);
            pp[7] = pp[6] + __popcll(k6);
        }
    }
    __syncthreads();

    // --- parallel selection ---
    if (tid < NMS_MAX) {
        int w = tid >> 6, bit = tid & 63;
        unsigned long long below = keepw[w] & below_mask(bit);
        int keptBefore = pp[w] + __popcll(below);
        bool kept = (keepw[w] >> bit) & 1ULL;
        int K = pp[MASKW];
        if (kept) {
            if (keptBefore < NUM_PRED) { sel[keptBefore] = tid; selk[keptBefore] = 1; }
        } else {
            int r = K + (tid - keptBefore);
            if (r < NUM_PRED) { sel[r] = tid; selk[r] = 0; }
        }
    }
    __syncthreads();

    // --- output rows: [score, box4, quad8] ---
    if (tid < NUM_PRED) {
        int i = sel[tid];
        float* o = out + ((size_t)b * NUM_PRED + tid) * 13;
        o[0] = selk[tid] ? scs[i] : -1.0f;
        o[1] = g_bx[b][i*4+0]; o[2] = g_bx[b][i*4+1];
        o[3] = g_bx[b][i*4+2]; o[4] = g_bx[b][i*4+3];
        const float* r = y + ((size_t)b * NBOX + g_sidx[b][i]) * NCH;
        float dcx = r[14], dcy = r[15], dw = r[16], dh = r[17];
        float v0 = r[18], v1 = r[19];
        float dqx[4] = {dcx - dw*0.5f, dcx + dw*0.5f, dcx + dw*0.5f, dcx - dw*0.5f};
        float dqy[4] = {dcy - dh*0.5f, dcy - dh*0.5f, dcy + dh*0.5f, dcy + dh*0.5f};
#pragma unroll
        for (int k = 0; k < 4; ++k) {
            float qx = dqx[k] + r[6 + 2*k] * v0 * dw;
            float qy = dqy[k] + r[7 + 2*k] * v1 * dh;
            o[5 + 2*k]     = qx * 384.0f;
            o[5 + 2*k + 1] = qy * 384.0f;
        }
    }
}

// ---------------- launch ---------------------------------------------------
extern "C" void kernel_launch(void* const* d_in, const int* in_sizes, int n_in,
                              void* d_out, int out_size) {
    const float* y = (const float*)d_in[0];
    float* out = (float*)d_out;
    k_extract<<<dim3(HBLK, BATCH), 256>>>(y);
    k_cut<<<BATCH, 1024>>>();
    k_gather<<<dim3(32, BATCH), 256>>>();
    k_sortdecode<<<BATCH, 1024>>>(y);
    k_iou<<<dim3(MASKW, BATCH), 256>>>();
    k_greedy<<<BATCH, 512>>>(y, out);
}